// round 3
// baseline (speedup 1.0000x reference)
#include <cuda_runtime.h>
#include <math.h>

#define BB 2
#define TT 2048
#define EE 768
#define HH 12
#define DH 64
#define VV 50257
#define NTOK (BB*TT)      // 4096
#define BH (BB*HH)        // 24

// ---------------- scratch (device globals; no allocation allowed) ----------
__device__ float g_h[NTOK*EE];                       // 12.6 MB  embed output
__device__ float g_q[BH*TT*DH];                      // 12.6 MB
__device__ float g_k[BH*TT*DH];
__device__ float g_v[BH*TT*DH];
__device__ float g_att[100663296];                   // 402 MB raw scores [bh][t][s]
__device__ float g_cmax[BH*TT];                      // per-column max
__device__ float g_cinv[BH*TT];                      // per-column 1/sumexp
__device__ float g_o[NTOK*EE];                       // concat-head attention out
__device__ float g_rowloss[NTOK];

// ---------------- K1: embed -------------------------------------------------
__global__ void k_embed(const int* __restrict__ x, const float* __restrict__ tok,
                        const float* __restrict__ pos) {
    int idx = blockIdx.x * 256 + threadIdx.x;          // over NTOK*EE
    int e  = idx % EE;
    int bt = idx / EE;
    int t  = bt % TT;
    g_h[idx] = tok[(size_t)x[bt] * EE + e] + pos[t * EE + e];
}

// ---------------- K2: per-head projection  out[bh][t][d] --------------------
// grid (TT/128, BH); 256 thr; tile 128(t) x 64(d), BK=16
__global__ __launch_bounds__(256) void k_proj(const float* __restrict__ W, int sel) {
    __shared__ float Hs[128][16];
    __shared__ float Ws[16][64];
    int bh = blockIdx.y;
    int b = bh / HH, h = bh % HH;
    int t0 = blockIdx.x * 128;
    const float* Aptr = g_h + ((size_t)b * TT + t0) * EE;
    const float* Wptr = W + (size_t)h * EE * DH;
    float* out = (sel == 0 ? g_q : (sel == 1 ? g_k : g_v));
    int tid = threadIdx.x;
    int tx = tid & 15, ty = tid >> 4;
    float acc[8][4];
    #pragma unroll
    for (int i = 0; i < 8; i++)
        #pragma unroll
        for (int j = 0; j < 4; j++) acc[i][j] = 0.f;

    for (int k0 = 0; k0 < EE; k0 += 16) {
        #pragma unroll
        for (int i = 0; i < 8; i++) {
            int id = tid + i * 256;
            int m = id >> 4, kk = id & 15;
            Hs[m][kk] = Aptr[(size_t)m * EE + k0 + kk];
        }
        #pragma unroll
        for (int i = 0; i < 4; i++) {
            int id = tid + i * 256;
            int kk = id >> 6, d = id & 63;
            Ws[kk][d] = Wptr[(size_t)(k0 + kk) * DH + d];
        }
        __syncthreads();
        #pragma unroll
        for (int kk = 0; kk < 16; kk++) {
            float a[8], bb[4];
            #pragma unroll
            for (int i = 0; i < 8; i++) a[i] = Hs[ty * 8 + i][kk];
            #pragma unroll
            for (int j = 0; j < 4; j++) bb[j] = Ws[kk][tx * 4 + j];
            #pragma unroll
            for (int i = 0; i < 8; i++)
                #pragma unroll
                for (int j = 0; j < 4; j++) acc[i][j] += a[i] * bb[j];
        }
        __syncthreads();
    }
    float* optr = out + ((size_t)bh * TT + t0) * DH;
    #pragma unroll
    for (int i = 0; i < 8; i++)
        #pragma unroll
        for (int j = 0; j < 4; j++)
            optr[(size_t)(ty * 8 + i) * DH + tx * 4 + j] = acc[i][j];
}

// ---------------- K3: raw scores att[bh][t][s] = 8 * q[t].k[s] --------------
// grid (TT/64 s, TT/64 t, BH); lower-triangle tiles only
__global__ __launch_bounds__(256) void k_scores() {
    int bh = blockIdx.z;
    int s0 = blockIdx.x * 64, t0 = blockIdx.y * 64;
    if (s0 > t0 + 63) return;                      // fully masked tile
    __shared__ float Qs[64][64];
    __shared__ float Ks[64][65];
    const float* q = g_q + (size_t)bh * TT * DH;
    const float* k = g_k + (size_t)bh * TT * DH;
    int tid = threadIdx.x;
    int tx = tid & 15, ty = tid >> 4;
    #pragma unroll
    for (int i = 0; i < 16; i++) {
        int id = tid + i * 256;
        int r = id >> 6, c = id & 63;
        Qs[r][c] = q[(size_t)(t0 + r) * DH + c];
        Ks[r][c] = k[(size_t)(s0 + r) * DH + c];
    }
    __syncthreads();
    float acc[4][4];
    #pragma unroll
    for (int i = 0; i < 4; i++)
        #pragma unroll
        for (int j = 0; j < 4; j++) acc[i][j] = 0.f;
    #pragma unroll
    for (int kk = 0; kk < 64; kk++) {
        float a[4], bb[4];
        #pragma unroll
        for (int i = 0; i < 4; i++) a[i] = Qs[ty * 4 + i][kk];
        #pragma unroll
        for (int j = 0; j < 4; j++) bb[j] = Ks[tx * 4 + j][kk];
        #pragma unroll
        for (int i = 0; i < 4; i++)
            #pragma unroll
            for (int j = 0; j < 4; j++) acc[i][j] += a[i] * bb[j];
    }
    float* out = g_att + (size_t)bh * TT * TT;
    #pragma unroll
    for (int i = 0; i < 4; i++)
        #pragma unroll
        for (int j = 0; j < 4; j++)
            out[(size_t)(t0 + ty * 4 + i) * TT + s0 + tx * 4 + j] = acc[i][j] * 8.0f;
}

// ---------------- K4: per-COLUMN (query-axis softmax!) stats ----------------
// grid (TT/256, BH); column s: max/sumexp over t in [s, TT)
__global__ void k_colstats() {
    int bh = blockIdx.y;
    int s0 = blockIdx.x * 256;
    int s = s0 + threadIdx.x;
    const float* base = g_att + (size_t)bh * TT * TT;
    float m = -1e30f, sum = 0.f;
    for (int t = s0; t < TT; ++t) {
        if (t >= s) {
            float v = base[(size_t)t * TT + s];
            float nm = fmaxf(m, v);
            sum = sum * __expf(m - nm) + __expf(v - nm);
            m = nm;
        }
    }
    g_cmax[bh * TT + s] = m;
    g_cinv[bh * TT + s] = 1.0f / sum;
}

// ---------------- K5: o = softmax(att) @ v (exp fused into tile load) -------
// grid (TT/64, BH); tile 64(t) x 64(d), BK=64(s)
__global__ __launch_bounds__(256) void k_av() {
    int bh = blockIdx.y;
    int b = bh / HH, h = bh % HH;
    int t0 = blockIdx.x * 64;
    __shared__ float Aw[64][64];   // [t][s] normalized weights
    __shared__ float Vs[64][64];   // [s][d]
    const float* att = g_att + (size_t)bh * TT * TT;
    const float* v   = g_v + (size_t)bh * TT * DH;
    const float* cm  = g_cmax + bh * TT;
    const float* ci  = g_cinv + bh * TT;
    int tid = threadIdx.x;
    int tx = tid & 15, ty = tid >> 4;
    float acc[4][4];
    #pragma unroll
    for (int i = 0; i < 4; i++)
        #pragma unroll
        for (int j = 0; j < 4; j++) acc[i][j] = 0.f;

    for (int s0 = 0; s0 <= t0 + 63; s0 += 64) {
        #pragma unroll
        for (int i = 0; i < 16; i++) {
            int id = tid + i * 256;
            int m = id >> 6, kk = id & 63;
            int t = t0 + m, s = s0 + kk;
            float w = 0.f;
            if (s <= t) {
                float sc = att[(size_t)t * TT + s];
                w = __expf(sc - cm[s]) * ci[s];
            }
            Aw[m][kk] = w;
            Vs[m][kk] = v[(size_t)(s0 + m) * DH + kk];  // m<->row(s), kk<->d
        }
        __syncthreads();
        #pragma unroll
        for (int kk = 0; kk < 64; kk++) {
            float a[4], bb[4];
            #pragma unroll
            for (int i = 0; i < 4; i++) a[i] = Aw[ty * 4 + i][kk];
            #pragma unroll
            for (int j = 0; j < 4; j++) bb[j] = Vs[kk][tx * 4 + j];
            #pragma unroll
            for (int i = 0; i < 4; i++)
                #pragma unroll
                for (int j = 0; j < 4; j++) acc[i][j] += a[i] * bb[j];
        }
        __syncthreads();
    }
    // write concat-head layout: o[b][t][h*64 + d]
    float* optr = g_o + ((size_t)b * TT + t0) * EE + h * DH;
    #pragma unroll
    for (int i = 0; i < 4; i++)
        #pragma unroll
        for (int j = 0; j < 4; j++)
            optr[(size_t)(ty * 4 + i) * EE + tx * 4 + j] = acc[i][j];
}

// ---------------- K6: logits = o @ Wout + bout  (the big one) ---------------
// grid (ceil(V/128), NTOK/128); 256 thr; tile 128x128, BK=8, 8x8 per thread
__global__ __launch_bounds__(256, 2) void k_logits(const float* __restrict__ Bm,
                                                   const float* __restrict__ bias,
                                                   float* __restrict__ C) {
    __shared__ __align__(16) float As[128][9];     // [m][k] padded
    __shared__ __align__(16) float Bs[8][128];     // [k][n]
    int n0 = blockIdx.x * 128;
    int m0 = blockIdx.y * 128;
    int tid = threadIdx.x;
    int tx = tid & 15, ty = tid >> 4;
    int arow = tid >> 1;
    int akq  = (tid & 1) * 4;
    int bk = tid >> 5;
    int bn = tid & 31;
    float acc[8][8];
    #pragma unroll
    for (int i = 0; i < 8; i++)
        #pragma unroll
        for (int j = 0; j < 8; j++) acc[i][j] = 0.f;

    const float* A = g_o;
    for (int k0 = 0; k0 < EE; k0 += 8) {
        float4 av = *(const float4*)(A + (size_t)(m0 + arow) * EE + k0 + akq);
        As[arow][akq + 0] = av.x;
        As[arow][akq + 1] = av.y;
        As[arow][akq + 2] = av.z;
        As[arow][akq + 3] = av.w;
        const float* brow = Bm + (size_t)(k0 + bk) * VV + n0;
        #pragma unroll
        for (int j = 0; j < 4; j++) {
            int n = bn + j * 32;
            Bs[bk][n] = (n0 + n < VV) ? brow[n] : 0.f;
        }
        __syncthreads();
        #pragma unroll
        for (int kk = 0; kk < 8; kk++) {
            float a[8], b[8];
            #pragma unroll
            for (int i = 0; i < 8; i++) a[i] = As[ty * 8 + i][kk];
            *(float4*)&b[0] = *(const float4*)&Bs[kk][tx * 8];
            *(float4*)&b[4] = *(const float4*)&Bs[kk][tx * 8 + 4];
            #pragma unroll
            for (int i = 0; i < 8; i++)
                #pragma unroll
                for (int j = 0; j < 8; j++) acc[i][j] += a[i] * b[j];
        }
        __syncthreads();
    }
    #pragma unroll
    for (int i = 0; i < 8; i++) {
        size_t m = m0 + ty * 8 + i;
        #pragma unroll
        for (int j = 0; j < 8; j++) {
            int n = n0 + tx * 8 + j;
            if (n < VV) C[m * VV + n] = acc[i][j] + bias[n];
        }
    }
}

// ---------------- K7: per-row logsumexp + target gather ---------------------
__global__ __launch_bounds__(256) void k_rowloss(const float* __restrict__ logits,
                                                 const int* __restrict__ y) {
    int row = blockIdx.x;
    const float* p = logits + (size_t)row * VV;
    int tid = threadIdx.x;
    float m = -1e30f, s = 0.f;
    for (int i = tid; i < VV; i += 256) {
        float v = p[i];
        float nm = fmaxf(m, v);
        s = s * __expf(m - nm) + __expf(v - nm);
        m = nm;
    }
    __shared__ float sm[256], ss[256];
    sm[tid] = m; ss[tid] = s;
    __syncthreads();
    for (int off = 128; off > 0; off >>= 1) {
        if (tid < off) {
            float m1 = sm[tid], s1 = ss[tid];
            float m2 = sm[tid + off], s2 = ss[tid + off];
            float nm = fmaxf(m1, m2);
            sm[tid] = nm;
            ss[tid] = s1 * __expf(m1 - nm) + s2 * __expf(m2 - nm);
        }
        __syncthreads();
    }
    if (tid == 0) {
        float lse = sm[0] + logf(ss[0]);
        g_rowloss[row] = lse - p[y[row]];
    }
}

// ---------------- K8: mean -> loss scalar -----------------------------------
__global__ void k_loss(float* __restrict__ out) {
    __shared__ float sb[256];
    int tid = threadIdx.x;
    float s = 0.f;
    for (int i = tid; i < NTOK; i += 256) s += g_rowloss[i];
    sb[tid] = s;
    __syncthreads();
    for (int off = 128; off > 0; off >>= 1) {
        if (tid < off) sb[tid] += sb[tid + off];
        __syncthreads();
    }
    if (tid == 0) out[0] = sb[0] / (float)NTOK;
}

// ---------------- launch -----------------------------------------------------
extern "C" void kernel_launch(void* const* d_in, const int* in_sizes, int n_in,
                              void* d_out, int out_size) {
    const int*   x    = (const int*)d_in[0];
    const int*   y    = (const int*)d_in[1];
    const float* tok  = (const float*)d_in[2];
    const float* pos  = (const float*)d_in[3];
    const float* Wq   = (const float*)d_in[4];
    const float* Wk   = (const float*)d_in[5];
    const float* Wv   = (const float*)d_in[6];
    const float* Wout = (const float*)d_in[7];
    const float* bout = (const float*)d_in[8];
    float* out = (float*)d_out;

    k_embed<<<NTOK * EE / 256, 256>>>(x, tok, pos);

    dim3 g2(TT / 128, BH);
    k_proj<<<g2, 256>>>(Wq, 0);
    k_proj<<<g2, 256>>>(Wk, 1);
    k_proj<<<g2, 256>>>(Wv, 2);

    dim3 g3(TT / 64, TT / 64, BH);
    k_scores<<<g3, 256>>>();

    dim3 g4(TT / 256, BH);
    k_colstats<<<g4, 256>>>();

    dim3 g5(TT / 64, BH);
    k_av<<<g5, 256>>>();

    dim3 g6((VV + 127) / 128, NTOK / 128);
    k_logits<<<g6, 256>>>(Wout, bout, out);

    k_rowloss<<<NTOK, 256>>>(out, y);

    long long nlogits = (long long)NTOK * VV;
    if ((long long)out_size > nlogits) {
        k_loss<<<1, 256>>>(out + nlogits);
    }
}

// round 5
// speedup vs baseline: 2.5213x; 2.5213x over previous
#include <cuda_runtime.h>
#include <cuda_bf16.h>
#include <math.h>
#include <stdint.h>

#define BB 2
#define TT 2048
#define EE 768
#define HH 12
#define DH 64
#define VV 50257
#define NTOK (BB*TT)      // 4096
#define BH (BB*HH)        // 24

// ---------------- scratch (device globals; no allocation allowed) ----------
__device__ float g_h[NTOK*EE];                       // embed output
__device__ float g_q[BH*TT*DH];
__device__ float g_k[BH*TT*DH];
__device__ float g_v[BH*TT*DH];
__device__ float g_att[100663296];                   // 402 MB raw scores [bh][t][s]
__device__ float g_cmax[BH*TT];
__device__ float g_cinv[BH*TT];
__device__ float g_o[NTOK*EE];
__device__ float g_rowloss[NTOK];
// bf16 hi/lo operands for the HMMA logits GEMM
__device__ __nv_bfloat16 gA_hi[NTOK*EE];
__device__ __nv_bfloat16 gA_lo[NTOK*EE];
__device__ __nv_bfloat16 gW_hi[(size_t)VV*EE];       // W^T [V][E] K-major
__device__ __nv_bfloat16 gW_lo[(size_t)VV*EE];

// ---------------- PTX helpers ----------------------------------------------
__device__ __forceinline__ uint32_t smem_u32(const void* p) {
    uint32_t a;
    asm("{ .reg .u64 t; cvta.to.shared.u64 t, %1; cvt.u32.u64 %0, t; }" : "=r"(a) : "l"(p));
    return a;
}
__device__ __forceinline__ void cpasync16(uint32_t s, const void* g) {
    asm volatile("cp.async.cg.shared.global [%0], [%1], 16;" :: "r"(s), "l"(g));
}
#define CP_COMMIT() asm volatile("cp.async.commit_group;" ::: "memory")
#define CP_WAIT1()  asm volatile("cp.async.wait_group 1;" ::: "memory")
#define CP_WAIT0()  asm volatile("cp.async.wait_group 0;" ::: "memory")

#define LDSM_X4(r, addr) \
    asm volatile("ldmatrix.sync.aligned.m8n8.x4.shared.b16 {%0,%1,%2,%3}, [%4];" \
        : "=r"((r)[0]), "=r"((r)[1]), "=r"((r)[2]), "=r"((r)[3]) : "r"(addr))

#define MMA16816(c, a, b0, b1) \
    asm volatile("mma.sync.aligned.m16n8k16.row.col.f32.bf16.bf16.f32 " \
        "{%0,%1,%2,%3}, {%4,%5,%6,%7}, {%8,%9}, {%0,%1,%2,%3};" \
        : "+f"((c)[0]), "+f"((c)[1]), "+f"((c)[2]), "+f"((c)[3]) \
        : "r"((a)[0]), "r"((a)[1]), "r"((a)[2]), "r"((a)[3]), "r"(b0), "r"(b1))

// ---------------- K1: embed -------------------------------------------------
__global__ void k_embed(const int* __restrict__ x, const float* __restrict__ tok,
                        const float* __restrict__ pos) {
    int idx = blockIdx.x * 256 + threadIdx.x;
    int e  = idx % EE;
    int bt = idx / EE;
    int t  = bt % TT;
    g_h[idx] = tok[(size_t)x[bt] * EE + e] + pos[t * EE + e];
}

// ---------------- K2: per-head projection -----------------------------------
__global__ __launch_bounds__(256) void k_proj(const float* __restrict__ W, int sel) {
    __shared__ float Hs[128][16];
    __shared__ float Ws[16][64];
    int bh = blockIdx.y;
    int b = bh / HH, h = bh % HH;
    int t0 = blockIdx.x * 128;
    const float* Aptr = g_h + ((size_t)b * TT + t0) * EE;
    const float* Wptr = W + (size_t)h * EE * DH;
    float* out = (sel == 0 ? g_q : (sel == 1 ? g_k : g_v));
    int tid = threadIdx.x;
    int tx = tid & 15, ty = tid >> 4;
    float acc[8][4];
    #pragma unroll
    for (int i = 0; i < 8; i++)
        #pragma unroll
        for (int j = 0; j < 4; j++) acc[i][j] = 0.f;

    for (int k0 = 0; k0 < EE; k0 += 16) {
        #pragma unroll
        for (int i = 0; i < 8; i++) {
            int id = tid + i * 256;
            int m = id >> 4, kk = id & 15;
            Hs[m][kk] = Aptr[(size_t)m * EE + k0 + kk];
        }
        #pragma unroll
        for (int i = 0; i < 4; i++) {
            int id = tid + i * 256;
            int kk = id >> 6, d = id & 63;
            Ws[kk][d] = Wptr[(size_t)(k0 + kk) * DH + d];
        }
        __syncthreads();
        #pragma unroll
        for (int kk = 0; kk < 16; kk++) {
            float a[8], bb[4];
            #pragma unroll
            for (int i = 0; i < 8; i++) a[i] = Hs[ty * 8 + i][kk];
            #pragma unroll
            for (int j = 0; j < 4; j++) bb[j] = Ws[kk][tx * 4 + j];
            #pragma unroll
            for (int i = 0; i < 8; i++)
                #pragma unroll
                for (int j = 0; j < 4; j++) acc[i][j] += a[i] * bb[j];
        }
        __syncthreads();
    }
    float* optr = out + ((size_t)bh * TT + t0) * DH;
    #pragma unroll
    for (int i = 0; i < 8; i++)
        #pragma unroll
        for (int j = 0; j < 4; j++)
            optr[(size_t)(ty * 8 + i) * DH + tx * 4 + j] = acc[i][j];
}

// ---------------- K3: raw scores --------------------------------------------
__global__ __launch_bounds__(256) void k_scores() {
    int bh = blockIdx.z;
    int s0 = blockIdx.x * 64, t0 = blockIdx.y * 64;
    if (s0 > t0 + 63) return;
    __shared__ float Qs[64][64];
    __shared__ float Ks[64][65];
    const float* q = g_q + (size_t)bh * TT * DH;
    const float* k = g_k + (size_t)bh * TT * DH;
    int tid = threadIdx.x;
    int tx = tid & 15, ty = tid >> 4;
    #pragma unroll
    for (int i = 0; i < 16; i++) {
        int id = tid + i * 256;
        int r = id >> 6, c = id & 63;
        Qs[r][c] = q[(size_t)(t0 + r) * DH + c];
        Ks[r][c] = k[(size_t)(s0 + r) * DH + c];
    }
    __syncthreads();
    float acc[4][4];
    #pragma unroll
    for (int i = 0; i < 4; i++)
        #pragma unroll
        for (int j = 0; j < 4; j++) acc[i][j] = 0.f;
    #pragma unroll
    for (int kk = 0; kk < 64; kk++) {
        float a[4], bb[4];
        #pragma unroll
        for (int i = 0; i < 4; i++) a[i] = Qs[ty * 4 + i][kk];
        #pragma unroll
        for (int j = 0; j < 4; j++) bb[j] = Ks[tx * 4 + j][kk];
        #pragma unroll
        for (int i = 0; i < 4; i++)
            #pragma unroll
            for (int j = 0; j < 4; j++) acc[i][j] += a[i] * bb[j];
    }
    float* out = g_att + (size_t)bh * TT * TT;
    #pragma unroll
    for (int i = 0; i < 4; i++)
        #pragma unroll
        for (int j = 0; j < 4; j++)
            out[(size_t)(t0 + ty * 4 + i) * TT + s0 + tx * 4 + j] = acc[i][j] * 8.0f;
}

// ---------------- K4: per-column softmax stats ------------------------------
__global__ void k_colstats() {
    int bh = blockIdx.y;
    int s0 = blockIdx.x * 256;
    int s = s0 + threadIdx.x;
    const float* base = g_att + (size_t)bh * TT * TT;
    float m = -1e30f, sum = 0.f;
    for (int t = s0; t < TT; ++t) {
        if (t >= s) {
            float v = base[(size_t)t * TT + s];
            float nm = fmaxf(m, v);
            sum = sum * __expf(m - nm) + __expf(v - nm);
            m = nm;
        }
    }
    g_cmax[bh * TT + s] = m;
    g_cinv[bh * TT + s] = 1.0f / sum;
}

// ---------------- K5: o = softmax(att) @ v ----------------------------------
__global__ __launch_bounds__(256) void k_av() {
    int bh = blockIdx.y;
    int b = bh / HH, h = bh % HH;
    int t0 = blockIdx.x * 64;
    __shared__ float Aw[64][64];
    __shared__ float Vs[64][64];
    const float* att = g_att + (size_t)bh * TT * TT;
    const float* v   = g_v + (size_t)bh * TT * DH;
    const float* cm  = g_cmax + bh * TT;
    const float* ci  = g_cinv + bh * TT;
    int tid = threadIdx.x;
    int tx = tid & 15, ty = tid >> 4;
    float acc[4][4];
    #pragma unroll
    for (int i = 0; i < 4; i++)
        #pragma unroll
        for (int j = 0; j < 4; j++) acc[i][j] = 0.f;

    for (int s0 = 0; s0 <= t0 + 63; s0 += 64) {
        #pragma unroll
        for (int i = 0; i < 16; i++) {
            int id = tid + i * 256;
            int m = id >> 6, kk = id & 63;
            int t = t0 + m, s = s0 + kk;
            float w = 0.f;
            if (s <= t) {
                float sc = att[(size_t)t * TT + s];
                w = __expf(sc - cm[s]) * ci[s];
            }
            Aw[m][kk] = w;
            Vs[m][kk] = v[(size_t)(s0 + m) * DH + kk];
        }
        __syncthreads();
        #pragma unroll
        for (int kk = 0; kk < 64; kk++) {
            float a[4], bb[4];
            #pragma unroll
            for (int i = 0; i < 4; i++) a[i] = Aw[ty * 4 + i][kk];
            #pragma unroll
            for (int j = 0; j < 4; j++) bb[j] = Vs[kk][tx * 4 + j];
            #pragma unroll
            for (int i = 0; i < 4; i++)
                #pragma unroll
                for (int j = 0; j < 4; j++) acc[i][j] += a[i] * bb[j];
        }
        __syncthreads();
    }
    float* optr = g_o + ((size_t)b * TT + t0) * EE + h * DH;
    #pragma unroll
    for (int i = 0; i < 4; i++)
        #pragma unroll
        for (int j = 0; j < 4; j++)
            optr[(size_t)(ty * 4 + i) * EE + tx * 4 + j] = acc[i][j];
}

// ---------------- K6a: split A (g_o) into bf16 hi/lo ------------------------
__global__ void k_cvtA() {
    int idx = blockIdx.x * 256 + threadIdx.x;
    float v = g_o[idx];
    __nv_bfloat16 hi = __float2bfloat16_rn(v);
    gA_hi[idx] = hi;
    gA_lo[idx] = __float2bfloat16_rn(v - __bfloat162float(hi));
}

// ---------------- K6b: transpose Wout [E][V] -> [V][E] bf16 hi/lo -----------
__global__ __launch_bounds__(256) void k_cvtW(const float* __restrict__ W) {
    __shared__ float tile[32][33];
    int n0 = blockIdx.x * 32;
    int k0 = blockIdx.y * 32;
    int tx = threadIdx.x, ty = threadIdx.y;   // 32 x 8
    #pragma unroll
    for (int j = 0; j < 4; j++) {
        int k = k0 + ty + j * 8;
        int n = n0 + tx;
        tile[ty + j * 8][tx] = (n < VV) ? W[(size_t)k * VV + n] : 0.f;
    }
    __syncthreads();
    #pragma unroll
    for (int j = 0; j < 4; j++) {
        int n = n0 + ty + j * 8;
        if (n < VV) {
            float v = tile[tx][ty + j * 8];
            __nv_bfloat16 hi = __float2bfloat16_rn(v);
            size_t off = (size_t)n * EE + k0 + tx;
            gW_hi[off] = hi;
            gW_lo[off] = __float2bfloat16_rn(v - __bfloat162float(hi));
        }
    }
}

// ---------------- K6c: logits GEMM via mma.sync bf16 hi/lo, fp32 acc --------
// block tile 128(M) x 128(N), BK=32, 8 warps (warp tile 64x32), cp.async x2
#define GTM 128
#define GTN 128
#define GBK 32
#define GITER (EE / GBK)          // 24
#define GSTAGE 32768              // 4 tensors x 8KB (Ahi,Alo,Bhi,Blo)
#define GSMEM_BYTES (2 * GSTAGE)  // 64 KB

__global__ __launch_bounds__(256) void k_gemm(const float* __restrict__ bias,
                                              float* __restrict__ C) {
    extern __shared__ __align__(128) char smem[];
    const uint32_t sb = smem_u32(smem);
    const int tid = threadIdx.x;
    const int wid = tid >> 5, lane = tid & 31;
    const int m0 = blockIdx.x * GTM;
    const int n0 = blockIdx.y * GTN;
    const int wm0 = (wid & 1) * 64;    // warp m offset in tile
    const int wn0 = (wid >> 1) * 32;   // warp n offset in tile

    float acc[4][4][4];
    #pragma unroll
    for (int i = 0; i < 4; i++)
        #pragma unroll
        for (int j = 0; j < 4; j++)
            #pragma unroll
            for (int q = 0; q < 4; q++) acc[i][j][q] = 0.f;

    // per-thread load coords (2 vectors per tensor per thread)
    auto load_stage = [&](int p, int k0) {
        uint32_t base = sb + p * GSTAGE;
        int kbyte = k0 * 2;
        #pragma unroll
        for (int half = 0; half < 2; half++) {
            int j = tid + half * 256;
            int row = j >> 2, ch = j & 3;
            uint32_t soff = row * 64 + (((ch ^ (row & 3)) & 3) << 4);
            size_t ga = (size_t)(m0 + row) * (EE * 2) + kbyte + ch * 16;
            cpasync16(base + soff,         (const char*)gA_hi + ga);
            cpasync16(base + 8192 + soff,  (const char*)gA_lo + ga);
            int nn = n0 + row; if (nn >= VV) nn = VV - 1;
            size_t gb = (size_t)nn * (EE * 2) + kbyte + ch * 16;
            cpasync16(base + 16384 + soff, (const char*)gW_hi + gb);
            cpasync16(base + 24576 + soff, (const char*)gW_lo + gb);
        }
    };

    load_stage(0, 0);
    CP_COMMIT();

    for (int it = 0; it < GITER; it++) {
        int p = it & 1;
        if (it + 1 < GITER) {
            load_stage(p ^ 1, (it + 1) * GBK);
            CP_COMMIT();
            CP_WAIT1();
        } else {
            CP_WAIT0();
        }
        __syncthreads();

        uint32_t stage = sb + p * GSTAGE;
        #pragma unroll
        for (int kh = 0; kh < 2; kh++) {
            uint32_t aH[4][4], aL[4][4], bHf[2][4], bLf[2][4];
            #pragma unroll
            for (int mf = 0; mf < 4; mf++) {
                int row = wm0 + mf * 16 + (lane & 7) + ((lane >> 3) & 1) * 8;
                int ch = 2 * kh + (lane >> 4);
                uint32_t ad = stage + row * 64 + (((ch ^ (row & 3)) & 3) << 4);
                LDSM_X4(aH[mf], ad);
                LDSM_X4(aL[mf], ad + 8192);
            }
            #pragma unroll
            for (int g = 0; g < 2; g++) {
                int row = wn0 + g * 16 + (lane & 7) + ((lane >> 4) & 1) * 8;
                int ch = 2 * kh + ((lane >> 3) & 1);
                uint32_t ad = stage + 16384 + row * 64 + (((ch ^ (row & 3)) & 3) << 4);
                LDSM_X4(bHf[g], ad);
                LDSM_X4(bLf[g], ad + 8192);
            }
            #pragma unroll
            for (int mf = 0; mf < 4; mf++)
                #pragma unroll
                for (int g = 0; g < 2; g++)
                    #pragma unroll
                    for (int nh = 0; nh < 2; nh++) {
                        float* c = acc[mf][g * 2 + nh];
                        MMA16816(c, aH[mf], bHf[g][nh * 2], bHf[g][nh * 2 + 1]);
                        MMA16816(c, aH[mf], bLf[g][nh * 2], bLf[g][nh * 2 + 1]);
                        MMA16816(c, aL[mf], bHf[g][nh * 2], bHf[g][nh * 2 + 1]);
                    }
        }
        __syncthreads();
    }

    // epilogue
    #pragma unroll
    for (int mf = 0; mf < 4; mf++) {
        int r = m0 + wm0 + mf * 16 + (lane >> 2);
        float* p0 = C + (size_t)r * VV;
        float* p1 = p0 + (size_t)8 * VV;
        #pragma unroll
        for (int nf = 0; nf < 4; nf++) {
            int cc = n0 + wn0 + nf * 8 + (lane & 3) * 2;
            float* a = acc[mf][nf];
            if (cc < VV) {
                float bv = __ldg(&bias[cc]);
                p0[cc] = a[0] + bv;
                p1[cc] = a[2] + bv;
            }
            if (cc + 1 < VV) {
                float bv = __ldg(&bias[cc + 1]);
                p0[cc + 1] = a[1] + bv;
                p1[cc + 1] = a[3] + bv;
            }
        }
    }
}

// ---------------- K7: per-row logsumexp + target gather ---------------------
__global__ __launch_bounds__(256) void k_rowloss(const float* __restrict__ logits,
                                                 const int* __restrict__ y) {
    int row = blockIdx.x;
    const float* p = logits + (size_t)row * VV;
    int tid = threadIdx.x;
    float m = -1e30f, s = 0.f;
    for (int i = tid; i < VV; i += 256) {
        float v = p[i];
        float nm = fmaxf(m, v);
        s = s * __expf(m - nm) + __expf(v - nm);
        m = nm;
    }
    __shared__ float sm[256], ss[256];
    sm[tid] = m; ss[tid] = s;
    __syncthreads();
    for (int off = 128; off > 0; off >>= 1) {
        if (tid < off) {
            float m1 = sm[tid], s1 = ss[tid];
            float m2 = sm[tid + off], s2 = ss[tid + off];
            float nm = fmaxf(m1, m2);
            sm[tid] = nm;
            ss[tid] = s1 * __expf(m1 - nm) + s2 * __expf(m2 - nm);
        }
        __syncthreads();
    }
    if (tid == 0) {
        float lse = sm[0] + logf(ss[0]);
        g_rowloss[row] = lse - p[y[row]];
    }
}

// ---------------- K8: mean -> loss scalar -----------------------------------
__global__ void k_loss(float* __restrict__ out) {
    __shared__ float sb[256];
    int tid = threadIdx.x;
    float s = 0.f;
    for (int i = tid; i < NTOK; i += 256) s += g_rowloss[i];
    sb[tid] = s;
    __syncthreads();
    for (int off = 128; off > 0; off >>= 1) {
        if (tid < off) sb[tid] += sb[tid + off];
        __syncthreads();
    }
    if (tid == 0) out[0] = sb[0] / (float)NTOK;
}

// ---------------- launch -----------------------------------------------------
extern "C" void kernel_launch(void* const* d_in, const int* in_sizes, int n_in,
                              void* d_out, int out_size) {
    const int*   x    = (const int*)d_in[0];
    const int*   y    = (const int*)d_in[1];
    const float* tok  = (const float*)d_in[2];
    const float* pos  = (const float*)d_in[3];
    const float* Wq   = (const float*)d_in[4];
    const float* Wk   = (const float*)d_in[5];
    const float* Wv   = (const float*)d_in[6];
    const float* Wout = (const float*)d_in[7];
    const float* bout = (const float*)d_in[8];
    float* out = (float*)d_out;

    cudaFuncSetAttribute(k_gemm, cudaFuncAttributeMaxDynamicSharedMemorySize,
                         GSMEM_BYTES);

    k_embed<<<NTOK * EE / 256, 256>>>(x, tok, pos);

    // W transpose/split is independent of the attention pipeline
    k_cvtW<<<dim3((VV + 31) / 32, EE / 32), dim3(32, 8)>>>(Wout);

    dim3 g2(TT / 128, BH);
    k_proj<<<g2, 256>>>(Wq, 0);
    k_proj<<<g2, 256>>>(Wk, 1);
    k_proj<<<g2, 256>>>(Wv, 2);

    dim3 g3(TT / 64, TT / 64, BH);
    k_scores<<<g3, 256>>>();

    dim3 g4(TT / 256, BH);
    k_colstats<<<g4, 256>>>();

    dim3 g5(TT / 64, BH);
    k_av<<<g5, 256>>>();

    k_cvtA<<<NTOK * EE / 256, 256>>>();

    dim3 g6(NTOK / GTM, (VV + GTN - 1) / GTN);   // m fast for B reuse in L2
    k_gemm<<<g6, 256, GSMEM_BYTES>>>(bout, out);

    k_rowloss<<<NTOK, 256>>>(out, y);

    long long nlogits = (long long)NTOK * VV;
    if ((long long)out_size > nlogits) {
        k_loss<<<1, 256>>>(out + nlogits);
    }
}

// round 6
// speedup vs baseline: 2.7872x; 1.1055x over previous
#include <cuda_runtime.h>
#include <cuda_bf16.h>
#include <math.h>
#include <stdint.h>

#define BB 2
#define TT 2048
#define EE 768
#define HH 12
#define DH 64
#define VV 50257
#define NTOK (BB*TT)      // 4096
#define BH (BB*HH)        // 24
#define NQKV 2304         // 3*H*Dh

// ---------------- scratch (device globals; no allocation allowed) ----------
__device__ float g_att[100663296];                   // 402 MB raw scores [bh][t][s]
__device__ float g_cmax[BH*TT];
__device__ float g_cinv[BH*TT];
__device__ float g_rowloss[NTOK];
__device__ __nv_bfloat16 g_hhi[NTOK*EE];             // embed hi/lo
__device__ __nv_bfloat16 g_hlo[NTOK*EE];
__device__ __nv_bfloat16 gWp_hi[NQKV*EE];            // packed QKV weights [n][e]
__device__ __nv_bfloat16 gWp_lo[NQKV*EE];
__device__ __nv_bfloat16 gq_hi[BH*TT*DH], gq_lo[BH*TT*DH];
__device__ __nv_bfloat16 gk_hi[BH*TT*DH], gk_lo[BH*TT*DH];
__device__ __nv_bfloat16 gvT_hi[BH*DH*TT], gvT_lo[BH*DH*TT];   // v transposed [bh][d][t]
__device__ __nv_bfloat16 gA_hi[NTOK*EE];             // attention out (A of logits GEMM)
__device__ __nv_bfloat16 gA_lo[NTOK*EE];
__device__ __nv_bfloat16 gW_hi[(size_t)VV*EE];       // Wout^T [V][E] K-major
__device__ __nv_bfloat16 gW_lo[(size_t)VV*EE];

// ---------------- PTX helpers ----------------------------------------------
__device__ __forceinline__ uint32_t smem_u32(const void* p) {
    uint32_t a;
    asm("{ .reg .u64 t; cvta.to.shared.u64 t, %1; cvt.u32.u64 %0, t; }" : "=r"(a) : "l"(p));
    return a;
}
__device__ __forceinline__ void cpasync16(uint32_t s, const void* g) {
    asm volatile("cp.async.cg.shared.global [%0], [%1], 16;" :: "r"(s), "l"(g));
}
#define CP_COMMIT() asm volatile("cp.async.commit_group;" ::: "memory")
#define CP_WAIT1()  asm volatile("cp.async.wait_group 1;" ::: "memory")
#define CP_WAIT0()  asm volatile("cp.async.wait_group 0;" ::: "memory")

#define LDSM_X4(r, addr) \
    asm volatile("ldmatrix.sync.aligned.m8n8.x4.shared.b16 {%0,%1,%2,%3}, [%4];" \
        : "=r"((r)[0]), "=r"((r)[1]), "=r"((r)[2]), "=r"((r)[3]) : "r"(addr))

#define MMA16816(c, a, b0, b1) \
    asm volatile("mma.sync.aligned.m16n8k16.row.col.f32.bf16.bf16.f32 " \
        "{%0,%1,%2,%3}, {%4,%5,%6,%7}, {%8,%9}, {%0,%1,%2,%3};" \
        : "+f"((c)[0]), "+f"((c)[1]), "+f"((c)[2]), "+f"((c)[3]) \
        : "r"((a)[0]), "r"((a)[1]), "r"((a)[2]), "r"((a)[3]), "r"(b0), "r"(b1))

__device__ __forceinline__ void split_bf16(float v, __nv_bfloat16& hi, __nv_bfloat16& lo) {
    hi = __float2bfloat16_rn(v);
    lo = __float2bfloat16_rn(v - __bfloat162float(hi));
}

// ---------------- K1: embed -> h hi/lo --------------------------------------
__global__ void k_embed(const int* __restrict__ x, const float* __restrict__ tok,
                        const float* __restrict__ pos) {
    int idx = blockIdx.x * 256 + threadIdx.x;
    int e  = idx % EE;
    int bt = idx / EE;
    int t  = bt % TT;
    float v = tok[(size_t)x[bt] * EE + e] + pos[t * EE + e];
    split_bf16(v, g_hhi[idx], g_hlo[idx]);
}

// ---------------- K2a: pack Wq/Wk/Wv -> [2304][768] bf16 hi/lo --------------
__global__ void k_packW(const float* __restrict__ Wq, const float* __restrict__ Wk,
                        const float* __restrict__ Wv) {
    int idx = blockIdx.x * 256 + threadIdx.x;       // over NQKV*EE
    int n = idx / EE, e = idx % EE;
    int mat = n / (HH * DH);
    int rem = n - mat * (HH * DH);
    int hh = rem >> 6, d = rem & 63;
    const float* W = (mat == 0 ? Wq : (mat == 1 ? Wk : Wv));
    float v = W[((size_t)hh * EE + e) * DH + d];
    split_bf16(v, gWp_hi[idx], gWp_lo[idx]);
}

// ---------------- K2b: transpose Wout [E][V] -> [V][E] bf16 hi/lo -----------
__global__ __launch_bounds__(256) void k_cvtW(const float* __restrict__ W) {
    __shared__ float tile[32][33];
    int n0 = blockIdx.x * 32;
    int k0 = blockIdx.y * 32;
    int tx = threadIdx.x, ty = threadIdx.y;   // 32 x 8
    #pragma unroll
    for (int j = 0; j < 4; j++) {
        int k = k0 + ty + j * 8;
        int n = n0 + tx;
        tile[ty + j * 8][tx] = (n < VV) ? W[(size_t)k * VV + n] : 0.f;
    }
    __syncthreads();
    #pragma unroll
    for (int j = 0; j < 4; j++) {
        int n = n0 + ty + j * 8;
        if (n < VV) {
            float v = tile[tx][ty + j * 8];
            size_t off = (size_t)n * EE + k0 + tx;
            split_bf16(v, gW_hi[off], gW_lo[off]);
        }
    }
}

// ---------------- K3: fused QKV projection (HMMA, hi/lo 3-pass) --------------
// A = h [4096][768], B = Wp [2304][768]; tile 128x128, BK=32, 8 warps
#define PSTAGE 32768
#define PSMEM  (2 * PSTAGE)
__global__ __launch_bounds__(256) void k_projmma() {
    extern __shared__ __align__(128) char smem[];
    const uint32_t sb = smem_u32(smem);
    const int tid = threadIdx.x;
    const int wid = tid >> 5, lane = tid & 31;
    const int m0 = blockIdx.x * 128;
    const int n0 = blockIdx.y * 128;
    const int wm0 = (wid & 1) * 64;
    const int wn0 = (wid >> 1) * 32;

    float acc[4][4][4];
    #pragma unroll
    for (int i = 0; i < 4; i++)
        #pragma unroll
        for (int j = 0; j < 4; j++)
            #pragma unroll
            for (int q = 0; q < 4; q++) acc[i][j][q] = 0.f;

    auto load_stage = [&](int p, int k0) {
        uint32_t base = sb + p * PSTAGE;
        int kbyte = k0 * 2;
        #pragma unroll
        for (int half = 0; half < 2; half++) {
            int j = tid + half * 256;
            int row = j >> 2, ch = j & 3;
            uint32_t soff = row * 64 + (((ch ^ (row & 3)) & 3) << 4);
            size_t ga = (size_t)(m0 + row) * (EE * 2) + kbyte + ch * 16;
            cpasync16(base + soff,         (const char*)g_hhi + ga);
            cpasync16(base + 8192 + soff,  (const char*)g_hlo + ga);
            size_t gb = (size_t)(n0 + row) * (EE * 2) + kbyte + ch * 16;
            cpasync16(base + 16384 + soff, (const char*)gWp_hi + gb);
            cpasync16(base + 24576 + soff, (const char*)gWp_lo + gb);
        }
    };

    load_stage(0, 0);
    CP_COMMIT();
    const int NIT = EE / 32;
    for (int it = 0; it < NIT; it++) {
        int p = it & 1;
        if (it + 1 < NIT) {
            load_stage(p ^ 1, (it + 1) * 32);
            CP_COMMIT();
            CP_WAIT1();
        } else {
            CP_WAIT0();
        }
        __syncthreads();
        uint32_t stage = sb + p * PSTAGE;
        #pragma unroll
        for (int kh = 0; kh < 2; kh++) {
            uint32_t aH[4][4], aL[4][4], bHf[2][4], bLf[2][4];
            #pragma unroll
            for (int mf = 0; mf < 4; mf++) {
                int row = wm0 + mf * 16 + (lane & 7) + ((lane >> 3) & 1) * 8;
                int ch = 2 * kh + (lane >> 4);
                uint32_t ad = stage + row * 64 + (((ch ^ (row & 3)) & 3) << 4);
                LDSM_X4(aH[mf], ad);
                LDSM_X4(aL[mf], ad + 8192);
            }
            #pragma unroll
            for (int g = 0; g < 2; g++) {
                int row = wn0 + g * 16 + (lane & 7) + ((lane >> 4) & 1) * 8;
                int ch = 2 * kh + ((lane >> 3) & 1);
                uint32_t ad = stage + 16384 + row * 64 + (((ch ^ (row & 3)) & 3) << 4);
                LDSM_X4(bHf[g], ad);
                LDSM_X4(bLf[g], ad + 8192);
            }
            #pragma unroll
            for (int mf = 0; mf < 4; mf++)
                #pragma unroll
                for (int g = 0; g < 2; g++)
                    #pragma unroll
                    for (int nh = 0; nh < 2; nh++) {
                        float* c = acc[mf][g * 2 + nh];
                        MMA16816(c, aH[mf], bHf[g][nh * 2], bHf[g][nh * 2 + 1]);
                        MMA16816(c, aH[mf], bLf[g][nh * 2], bLf[g][nh * 2 + 1]);
                        MMA16816(c, aL[mf], bHf[g][nh * 2], bHf[g][nh * 2 + 1]);
                    }
        }
        __syncthreads();
    }

    // epilogue: scatter to q/k hi/lo [bh][t][d] and v^T hi/lo [bh][d][t]
    const int mat = n0 / (HH * DH);     // tile never crosses a matrix boundary
    #pragma unroll
    for (int mf = 0; mf < 4; mf++) {
        int r0 = m0 + wm0 + mf * 16 + (lane >> 2);
        #pragma unroll
        for (int nf = 0; nf < 4; nf++) {
            float* a = acc[mf][nf];
            #pragma unroll
            for (int c2 = 0; c2 < 2; c2++) {
                int n = n0 + wn0 + nf * 8 + (lane & 3) * 2 + c2;
                int rem = n - mat * (HH * DH);
                int hh = rem >> 6, d = rem & 63;
                #pragma unroll
                for (int rr = 0; rr < 2; rr++) {
                    int r = r0 + rr * 8;
                    int b = r >> 11, t = r & 2047;
                    int bh = b * HH + hh;
                    float v = a[c2 + rr * 2];
                    __nv_bfloat16 hi, lo;
                    split_bf16(v, hi, lo);
                    if (mat == 0) {
                        size_t off = ((size_t)bh * TT + t) * DH + d;
                        gq_hi[off] = hi; gq_lo[off] = lo;
                    } else if (mat == 1) {
                        size_t off = ((size_t)bh * TT + t) * DH + d;
                        gk_hi[off] = hi; gk_lo[off] = lo;
                    } else {
                        size_t off = ((size_t)bh * DH + d) * TT + t;
                        gvT_hi[off] = hi; gvT_lo[off] = lo;
                    }
                }
            }
        }
    }
}

// ---------------- K4: scores via HMMA (128x128 tiles, K=64, 3-pass) ---------
// smem: qhi 16K, qlo 16K, khi 16K, klo 16K = 64KB; rows 128B, 8 chunks, xor&7
#define SSMEM 65536
__global__ __launch_bounds__(256) void k_scores() {
    int zs = blockIdx.x, zt = blockIdx.y, bh = blockIdx.z;
    if (zs > zt) return;
    int s0 = zs * 128, t0 = zt * 128;
    extern __shared__ __align__(128) char smem[];
    const uint32_t sb = smem_u32(smem);
    const int tid = threadIdx.x;
    const int wid = tid >> 5, lane = tid & 31;
    const int wm0 = (wid & 1) * 64;
    const int wn0 = (wid >> 1) * 32;

    // load q/k tiles (128 rows x 128B each, hi+lo)
    #pragma unroll
    for (int i = 0; i < 4; i++) {
        int j = tid + i * 256;                 // 0..1023
        int row = j >> 3, ch = j & 7;
        uint32_t soff = row * 128 + (((ch ^ (row & 7)) & 7) << 4);
        size_t gq = ((size_t)bh * TT + t0 + row) * 128 + ch * 16;
        size_t gk = ((size_t)bh * TT + s0 + row) * 128 + ch * 16;
        cpasync16(sb + soff,         (const char*)gq_hi + gq);
        cpasync16(sb + 16384 + soff, (const char*)gq_lo + gq);
        cpasync16(sb + 32768 + soff, (const char*)gk_hi + gk);
        cpasync16(sb + 49152 + soff, (const char*)gk_lo + gk);
    }
    CP_COMMIT();
    CP_WAIT0();
    __syncthreads();

    float acc[4][4][4];
    #pragma unroll
    for (int i = 0; i < 4; i++)
        #pragma unroll
        for (int j = 0; j < 4; j++)
            #pragma unroll
            for (int q = 0; q < 4; q++) acc[i][j][q] = 0.f;

    #pragma unroll
    for (int kh = 0; kh < 4; kh++) {
        uint32_t aH[4][4], aL[4][4], bHf[2][4], bLf[2][4];
        #pragma unroll
        for (int mf = 0; mf < 4; mf++) {
            int row = wm0 + mf * 16 + (lane & 7) + ((lane >> 3) & 1) * 8;
            int ch = 2 * kh + (lane >> 4);
            uint32_t ad = sb + row * 128 + (((ch ^ (row & 7)) & 7) << 4);
            LDSM_X4(aH[mf], ad);
            LDSM_X4(aL[mf], ad + 16384);
        }
        #pragma unroll
        for (int g = 0; g < 2; g++) {
            int row = wn0 + g * 16 + (lane & 7) + ((lane >> 4) & 1) * 8;
            int ch = 2 * kh + ((lane >> 3) & 1);
            uint32_t ad = sb + 32768 + row * 128 + (((ch ^ (row & 7)) & 7) << 4);
            LDSM_X4(bHf[g], ad);
            LDSM_X4(bLf[g], ad + 16384);
        }
        #pragma unroll
        for (int mf = 0; mf < 4; mf++)
            #pragma unroll
            for (int g = 0; g < 2; g++)
                #pragma unroll
                for (int nh = 0; nh < 2; nh++) {
                    float* c = acc[mf][g * 2 + nh];
                    MMA16816(c, aH[mf], bHf[g][nh * 2], bHf[g][nh * 2 + 1]);
                    MMA16816(c, aH[mf], bLf[g][nh * 2], bLf[g][nh * 2 + 1]);
                    MMA16816(c, aL[mf], bHf[g][nh * 2], bHf[g][nh * 2 + 1]);
                }
    }

    // store fp32 scores * 8 (no mask needed: consumers skip s>t)
    float* out = g_att + (size_t)bh * TT * TT;
    #pragma unroll
    for (int mf = 0; mf < 4; mf++) {
        int t = t0 + wm0 + mf * 16 + (lane >> 2);
        float* p0 = out + (size_t)t * TT;
        float* p1 = p0 + (size_t)8 * TT;
        #pragma unroll
        for (int nf = 0; nf < 4; nf++) {
            int s = s0 + wn0 + nf * 8 + (lane & 3) * 2;
            float* a = acc[mf][nf];
            p0[s]     = a[0] * 8.0f;
            p0[s + 1] = a[1] * 8.0f;
            p1[s]     = a[2] * 8.0f;
            p1[s + 1] = a[3] * 8.0f;
        }
    }
}

// ---------------- K5: per-column softmax stats ------------------------------
__global__ void k_colstats() {
    int bh = blockIdx.y;
    int s0 = blockIdx.x * 256;
    int s = s0 + threadIdx.x;
    const float* base = g_att + (size_t)bh * TT * TT;
    float m = -1e30f, sum = 0.f;
    for (int t = s0; t < TT; ++t) {
        if (t >= s) {
            float v = base[(size_t)t * TT + s];
            float nm = fmaxf(m, v);
            sum = sum * __expf(m - nm) + __expf(v - nm);
            m = nm;
        }
    }
    g_cmax[bh * TT + s] = m;
    g_cinv[bh * TT + s] = 1.0f / sum;
}

// ---------------- K6: o = softmax(att) @ v via HMMA -------------------------
// t-tile 128, N=64 (all d), s-chunks of 64; w split hi/lo on the fly
// smem: whi 16K, wlo 16K, vhi 8K, vlo 8K = 48KB
#define ASMEM 49152
__global__ __launch_bounds__(256) void k_av() {
    int zt = blockIdx.x, bh = blockIdx.y;
    int t0 = zt * 128;
    int b = bh / HH, h = bh % HH;
    extern __shared__ __align__(128) char smem[];
    const uint32_t sb = smem_u32(smem);
    __nv_bfloat16* whi = (__nv_bfloat16*)smem;
    __nv_bfloat16* wlo = (__nv_bfloat16*)(smem + 16384);
    const int tid = threadIdx.x;
    const int wid = tid >> 5, lane = tid & 31;
    const int wm0 = (wid & 3) * 32;
    const int wn0 = (wid >> 2) * 32;

    const float* att = g_att + (size_t)bh * TT * TT;
    const float* cm  = g_cmax + bh * TT;
    const float* ci  = g_cinv + bh * TT;

    float acc[2][4][4];
    #pragma unroll
    for (int i = 0; i < 2; i++)
        #pragma unroll
        for (int j = 0; j < 4; j++)
            #pragma unroll
            for (int q = 0; q < 4; q++) acc[i][j][q] = 0.f;

    int nchunks = 2 * zt + 2;
    for (int c = 0; c < nchunks; c++) {
        int s0 = c * 64;
        // v^T tile loads (64 d-rows x 128B, hi+lo)
        #pragma unroll
        for (int i = 0; i < 2; i++) {
            int j = tid + i * 256;             // 0..511
            int row = j >> 3, ch = j & 7;
            uint32_t soff = row * 128 + (((ch ^ (row & 7)) & 7) << 4);
            size_t gv = ((size_t)bh * DH + row) * (TT * 2) + s0 * 2 + ch * 16;
            cpasync16(sb + 32768 + soff, (const char*)gvT_hi + gv);
            cpasync16(sb + 40960 + soff, (const char*)gvT_lo + gv);
        }
        CP_COMMIT();
        // w tile: 128 t-rows x 64 s, fp32 -> hi/lo swizzled smem
        #pragma unroll
        for (int i = 0; i < 32; i++) {
            int j = tid + i * 256;             // 0..8191
            int row = j >> 6, sc = j & 63;
            int t = t0 + row, s = s0 + sc;
            float w = 0.f;
            if (s <= t) {
                w = __expf(att[(size_t)t * TT + s] - cm[s]) * ci[s];
            }
            __nv_bfloat16 hi, lo;
            split_bf16(w, hi, lo);
            int ch = sc >> 3;
            uint32_t soff = row * 128 + (((ch ^ (row & 7)) & 7) << 4) + (sc & 7) * 2;
            *(__nv_bfloat16*)((char*)whi + soff) = hi;
            *(__nv_bfloat16*)((char*)wlo + soff) = lo;
        }
        CP_WAIT0();
        __syncthreads();

        #pragma unroll
        for (int kh = 0; kh < 4; kh++) {
            uint32_t aH[2][4], aL[2][4], bHf[2][4], bLf[2][4];
            #pragma unroll
            for (int mf = 0; mf < 2; mf++) {
                int row = wm0 + mf * 16 + (lane & 7) + ((lane >> 3) & 1) * 8;
                int ch = 2 * kh + (lane >> 4);
                uint32_t ad = sb + row * 128 + (((ch ^ (row & 7)) & 7) << 4);
                LDSM_X4(aH[mf], ad);
                LDSM_X4(aL[mf], ad + 16384);
            }
            #pragma unroll
            for (int g = 0; g < 2; g++) {
                int row = wn0 + g * 16 + (lane & 7) + ((lane >> 4) & 1) * 8;
                int ch = 2 * kh + ((lane >> 3) & 1);
                uint32_t ad = sb + 32768 + row * 128 + (((ch ^ (row & 7)) & 7) << 4);
                LDSM_X4(bHf[g], ad);
                LDSM_X4(bLf[g], ad + 8192);
            }
            #pragma unroll
            for (int mf = 0; mf < 2; mf++)
                #pragma unroll
                for (int g = 0; g < 2; g++)
                    #pragma unroll
                    for (int nh = 0; nh < 2; nh++) {
                        float* cc = acc[mf][g * 2 + nh];
                        MMA16816(cc, aH[mf], bHf[g][nh * 2], bHf[g][nh * 2 + 1]);
                        MMA16816(cc, aH[mf], bLf[g][nh * 2], bLf[g][nh * 2 + 1]);
                        MMA16816(cc, aL[mf], bHf[g][nh * 2], bHf[g][nh * 2 + 1]);
                    }
        }
        __syncthreads();
    }

    // epilogue: o -> gA hi/lo at [b*TT+t][h*64+d]
    #pragma unroll
    for (int mf = 0; mf < 2; mf++) {
        int t = t0 + wm0 + mf * 16 + (lane >> 2);
        #pragma unroll
        for (int nf = 0; nf < 4; nf++) {
            int d = wn0 + nf * 8 + (lane & 3) * 2;
            float* a = acc[mf][nf];
            #pragma unroll
            for (int rr = 0; rr < 2; rr++) {
                int tt = t + rr * 8;
                size_t off = ((size_t)b * TT + tt) * EE + h * DH + d;
                __nv_bfloat16 hi, lo;
                split_bf16(a[rr * 2], hi, lo);
                gA_hi[off] = hi; gA_lo[off] = lo;
                split_bf16(a[rr * 2 + 1], hi, lo);
                gA_hi[off + 1] = hi; gA_lo[off + 1] = lo;
            }
        }
    }
}

// ---------------- K7: logits GEMM (unchanged HMMA) --------------------------
#define GSTAGE 32768
#define GSMEM_BYTES (2 * GSTAGE)
__global__ __launch_bounds__(256) void k_gemm(const float* __restrict__ bias,
                                              float* __restrict__ C) {
    extern __shared__ __align__(128) char smem[];
    const uint32_t sb = smem_u32(smem);
    const int tid = threadIdx.x;
    const int wid = tid >> 5, lane = tid & 31;
    const int m0 = blockIdx.x * 128;
    const int n0 = blockIdx.y * 128;
    const int wm0 = (wid & 1) * 64;
    const int wn0 = (wid >> 1) * 32;

    float acc[4][4][4];
    #pragma unroll
    for (int i = 0; i < 4; i++)
        #pragma unroll
        for (int j = 0; j < 4; j++)
            #pragma unroll
            for (int q = 0; q < 4; q++) acc[i][j][q] = 0.f;

    auto load_stage = [&](int p, int k0) {
        uint32_t base = sb + p * GSTAGE;
        int kbyte = k0 * 2;
        #pragma unroll
        for (int half = 0; half < 2; half++) {
            int j = tid + half * 256;
            int row = j >> 2, ch = j & 3;
            uint32_t soff = row * 64 + (((ch ^ (row & 3)) & 3) << 4);
            size_t ga = (size_t)(m0 + row) * (EE * 2) + kbyte + ch * 16;
            cpasync16(base + soff,         (const char*)gA_hi + ga);
            cpasync16(base + 8192 + soff,  (const char*)gA_lo + ga);
            int nn = n0 + row; if (nn >= VV) nn = VV - 1;
            size_t gb = (size_t)nn * (EE * 2) + kbyte + ch * 16;
            cpasync16(base + 16384 + soff, (const char*)gW_hi + gb);
            cpasync16(base + 24576 + soff, (const char*)gW_lo + gb);
        }
    };

    load_stage(0, 0);
    CP_COMMIT();
    const int NIT = EE / 32;
    for (int it = 0; it < NIT; it++) {
        int p = it & 1;
        if (it + 1 < NIT) {
            load_stage(p ^ 1, (it + 1) * 32);
            CP_COMMIT();
            CP_WAIT1();
        } else {
            CP_WAIT0();
        }
        __syncthreads();
        uint32_t stage = sb + p * GSTAGE;
        #pragma unroll
        for (int kh = 0; kh < 2; kh++) {
            uint32_t aH[4][4], aL[4][4], bHf[2][4], bLf[2][4];
            #pragma unroll
            for (int mf = 0; mf < 4; mf++) {
                int row = wm0 + mf * 16 + (lane & 7) + ((lane >> 3) & 1) * 8;
                int ch = 2 * kh + (lane >> 4);
                uint32_t ad = stage + row * 64 + (((ch ^ (row & 3)) & 3) << 4);
                LDSM_X4(aH[mf], ad);
                LDSM_X4(aL[mf], ad + 8192);
            }
            #pragma unroll
            for (int g = 0; g < 2; g++) {
                int row = wn0 + g * 16 + (lane & 7) + ((lane >> 4) & 1) * 8;
                int ch = 2 * kh + ((lane >> 3) & 1);
                uint32_t ad = stage + 16384 + row * 64 + (((ch ^ (row & 3)) & 3) << 4);
                LDSM_X4(bHf[g], ad);
                LDSM_X4(bLf[g], ad + 8192);
            }
            #pragma unroll
            for (int mf = 0; mf < 4; mf++)
                #pragma unroll
                for (int g = 0; g < 2; g++)
                    #pragma unroll
                    for (int nh = 0; nh < 2; nh++) {
                        float* c = acc[mf][g * 2 + nh];
                        MMA16816(c, aH[mf], bHf[g][nh * 2], bHf[g][nh * 2 + 1]);
                        MMA16816(c, aH[mf], bLf[g][nh * 2], bLf[g][nh * 2 + 1]);
                        MMA16816(c, aL[mf], bHf[g][nh * 2], bHf[g][nh * 2 + 1]);
                    }
        }
        __syncthreads();
    }

    #pragma unroll
    for (int mf = 0; mf < 4; mf++) {
        int r = m0 + wm0 + mf * 16 + (lane >> 2);
        float* p0 = C + (size_t)r * VV;
        float* p1 = p0 + (size_t)8 * VV;
        #pragma unroll
        for (int nf = 0; nf < 4; nf++) {
            int cc = n0 + wn0 + nf * 8 + (lane & 3) * 2;
            float* a = acc[mf][nf];
            if (cc < VV) {
                float bv = __ldg(&bias[cc]);
                p0[cc] = a[0] + bv;
                p1[cc] = a[2] + bv;
            }
            if (cc + 1 < VV) {
                float bv = __ldg(&bias[cc + 1]);
                p0[cc + 1] = a[1] + bv;
                p1[cc + 1] = a[3] + bv;
            }
        }
    }
}

// ---------------- K8: per-row logsumexp + target gather ---------------------
__global__ __launch_bounds__(256) void k_rowloss(const float* __restrict__ logits,
                                                 const int* __restrict__ y) {
    int row = blockIdx.x;
    const float* p = logits + (size_t)row * VV;
    int tid = threadIdx.x;
    float m = -1e30f, s = 0.f;
    for (int i = tid; i < VV; i += 256) {
        float v = p[i];
        float nm = fmaxf(m, v);
        s = s * __expf(m - nm) + __expf(v - nm);
        m = nm;
    }
    __shared__ float sm[256], ss[256];
    sm[tid] = m; ss[tid] = s;
    __syncthreads();
    for (int off = 128; off > 0; off >>= 1) {
        if (tid < off) {
            float m1 = sm[tid], s1 = ss[tid];
            float m2 = sm[tid + off], s2 = ss[tid + off];
            float nm = fmaxf(m1, m2);
            sm[tid] = nm;
            ss[tid] = s1 * __expf(m1 - nm) + s2 * __expf(m2 - nm);
        }
        __syncthreads();
    }
    if (tid == 0) {
        float lse = sm[0] + logf(ss[0]);
        g_rowloss[row] = lse - p[y[row]];
    }
}

// ---------------- K9: mean -> loss scalar -----------------------------------
__global__ void k_loss(float* __restrict__ out) {
    __shared__ float sb[256];
    int tid = threadIdx.x;
    float s = 0.f;
    for (int i = tid; i < NTOK; i += 256) s += g_rowloss[i];
    sb[tid] = s;
    __syncthreads();
    for (int off = 128; off > 0; off >>= 1) {
        if (tid < off) sb[tid] += sb[tid + off];
        __syncthreads();
    }
    if (tid == 0) out[0] = sb[0] / (float)NTOK;
}

// ---------------- launch -----------------------------------------------------
extern "C" void kernel_launch(void* const* d_in, const int* in_sizes, int n_in,
                              void* d_out, int out_size) {
    const int*   x    = (const int*)d_in[0];
    const int*   y    = (const int*)d_in[1];
    const float* tok  = (const float*)d_in[2];
    const float* pos  = (const float*)d_in[3];
    const float* Wq   = (const float*)d_in[4];
    const float* Wk   = (const float*)d_in[5];
    const float* Wv   = (const float*)d_in[6];
    const float* Wout = (const float*)d_in[7];
    const float* bout = (const float*)d_in[8];
    float* out = (float*)d_out;

    cudaFuncSetAttribute(k_projmma, cudaFuncAttributeMaxDynamicSharedMemorySize, PSMEM);
    cudaFuncSetAttribute(k_scores,  cudaFuncAttributeMaxDynamicSharedMemorySize, SSMEM);
    cudaFuncSetAttribute(k_av,      cudaFuncAttributeMaxDynamicSharedMemorySize, ASMEM);
    cudaFuncSetAttribute(k_gemm,    cudaFuncAttributeMaxDynamicSharedMemorySize, GSMEM_BYTES);

    k_embed<<<NTOK * EE / 256, 256>>>(x, tok, pos);
    k_packW<<<NQKV * EE / 256, 256>>>(Wq, Wk, Wv);
    k_cvtW<<<dim3((VV + 31) / 32, EE / 32), dim3(32, 8)>>>(Wout);

    k_projmma<<<dim3(NTOK / 128, NQKV / 128), 256, PSMEM>>>();

    k_scores<<<dim3(16, 16, BH), 256, SSMEM>>>();

    k_colstats<<<dim3(TT / 256, BH), 256>>>();

    k_av<<<dim3(TT / 128, BH), 256, ASMEM>>>();

    k_gemm<<<dim3(NTOK / 128, (VV + 127) / 128), 256, GSMEM_BYTES>>>(bout, out);

    k_rowloss<<<NTOK, 256>>>(out, y);

    long long nlogits = (long long)NTOK * VV;
    if ((long long)out_size > nlogits) {
        k_loss<<<1, 256>>>(out + nlogits);
    }
}